// round 6
// baseline (speedup 1.0000x reference)
#include <cuda_runtime.h>

// GMP forward:
// out[b,j] = sum_{i=0..7} xc[b, j+i-7] * F_i(j+i-7)
// F_i(n)   = W[i,0] + sum_{m=0..7} sum_{d=0..2} W[i,1+3m+d] * a(n+m-7)^(d+1)
// xc zero-extended for n<0; a(n)=|xc(n)| zero-extended.

constexpr int Bn  = 64;
constexpr int Tn  = 16384;
constexpr int Mm  = 8;
constexpr int CH  = 8;     // samples per thread
constexpr int TPB = 128;

__global__ __launch_bounds__(TPB)
void gmp_kernel(const float2* __restrict__ x,     // (B,T) complex as float2
                const float*  __restrict__ W,     // (8,25)
                float2*       __restrict__ out)   // (B,T) complex as float2
{
    __shared__ float sW[Mm * 25];
    for (int q = threadIdx.x; q < Mm * 25; q += TPB) sW[q] = W[q];
    __syncthreads();

    const int per_row = Tn / CH;                       // 2048
    const int idx = blockIdx.x * TPB + threadIdx.x;    // < B*per_row
    const int b   = idx / per_row;
    const int j0  = (idx - b * per_row) * CH;

    const float2* xrow = x + (size_t)b * Tn;

    // Load complex window: array index k corresponds to n = j0 + k - 14.
    float xr[CH + 14], xi[CH + 14];
#pragma unroll
    for (int k = 0; k < CH + 14; k++) {
        const int n = j0 + k - 14;
        float2 v;
        if (n >= 0) v = xrow[n];
        else        v = make_float2(0.f, 0.f);
        xr[k] = v.x; xi[k] = v.y;
    }

    // Envelope powers a^1, a^2, a^3 over the window.
    float a1[CH + 14], a2[CH + 14], a3[CH + 14];
#pragma unroll
    for (int k = 0; k < CH + 14; k++) {
        const float m2 = fmaf(xr[k], xr[k], xi[k] * xi[k]);
        const float a  = sqrtf(m2);
        a1[k] = a; a2[k] = m2; a3[k] = a * m2;
    }

    float or_[CH], oi_[CH];
#pragma unroll
    for (int c = 0; c < CH; c++) { or_[c] = 0.f; oi_[c] = 0.f; }

#pragma unroll
    for (int i = 0; i < Mm; i++) {
        const float w0 = sW[i * 25];
        float wd[24];
#pragma unroll
        for (int q = 0; q < 24; q++) wd[q] = sW[i * 25 + 1 + q];

#pragma unroll
        for (int c = 0; c < CH; c++) {
            float F = w0;
#pragma unroll
            for (int m = 0; m < Mm; m++) {
                const int t = c + i + m;      // a-index for n = j0+c+i+m-14
                F = fmaf(wd[m * 3 + 0], a1[t], F);
                F = fmaf(wd[m * 3 + 1], a2[t], F);
                F = fmaf(wd[m * 3 + 2], a3[t], F);
            }
            const int xk = c + i + 7;         // x-index for n = j0+c+i-7
            or_[c] = fmaf(xr[xk], F, or_[c]);
            oi_[c] = fmaf(xi[xk], F, oi_[c]);
        }
    }

    float2* orow = out + (size_t)b * Tn + j0;
#pragma unroll
    for (int c = 0; c < CH; c++) orow[c] = make_float2(or_[c], oi_[c]);
}

extern "C" void kernel_launch(void* const* d_in, const int* in_sizes, int n_in,
                              void* d_out, int out_size)
{
    const float2* x = (const float2*)d_in[0];
    // d_in[1] = h_0 (unused)
    const float*  W = (const float*)d_in[2];
    float2* out = (float2*)d_out;

    const int total_threads = Bn * (Tn / CH);      // 131072
    const int grid = total_threads / TPB;          // 1024
    gmp_kernel<<<grid, TPB>>>(x, W, out);
}

// round 7
// speedup vs baseline: 1.0122x; 1.0122x over previous
#include <cuda_runtime.h>

// GMP forward:
// out[b,j] = sum_{i=0..7} xc[b, j+i-7] * F_i(j+i-7)
// F_i(n)   = W[i,0] + sum_{m=0..7} sum_{d=0..2} W[i,1+3m+d] * a(n+m-7)^(d+1)
// xc zero-extended for n<0; a(n)=|xc(n)| zero-extended.

constexpr int Bn  = 64;
constexpr int Tn  = 16384;
constexpr int Mm  = 8;
constexpr int CH  = 8;     // samples per thread
constexpr int TPB = 128;

__global__ __launch_bounds__(TPB)
void gmp_kernel(const float2* __restrict__ x,     // (B,T) complex as float2
                const float*  __restrict__ W,     // (8,25)
                float2*       __restrict__ out)   // (B,T) complex as float2
{
    __shared__ float sW[Mm * 25];
    for (int q = threadIdx.x; q < Mm * 25; q += TPB) sW[q] = W[q];
    __syncthreads();

    const int per_row = Tn / CH;                       // 2048
    const int idx = blockIdx.x * TPB + threadIdx.x;    // < B*per_row
    const int b   = idx / per_row;
    const int j0  = (idx - b * per_row) * CH;

    const float2* xrow = x + (size_t)b * Tn;

    // Load complex window: array index k corresponds to n = j0 + k - 14.
    float xr[CH + 14], xi[CH + 14];
#pragma unroll
    for (int k = 0; k < CH + 14; k++) {
        const int n = j0 + k - 14;
        float2 v;
        if (n >= 0) v = xrow[n];
        else        v = make_float2(0.f, 0.f);
        xr[k] = v.x; xi[k] = v.y;
    }

    // Envelope powers a^1, a^2, a^3 over the window.
    float a1[CH + 14], a2[CH + 14], a3[CH + 14];
#pragma unroll
    for (int k = 0; k < CH + 14; k++) {
        const float m2 = fmaf(xr[k], xr[k], xi[k] * xi[k]);
        const float a  = sqrtf(m2);
        a1[k] = a; a2[k] = m2; a3[k] = a * m2;
    }

    float or_[CH], oi_[CH];
#pragma unroll
    for (int c = 0; c < CH; c++) { or_[c] = 0.f; oi_[c] = 0.f; }

#pragma unroll
    for (int i = 0; i < Mm; i++) {
        const float w0 = sW[i * 25];
        float wd[24];
#pragma unroll
        for (int q = 0; q < 24; q++) wd[q] = sW[i * 25 + 1 + q];

#pragma unroll
        for (int c = 0; c < CH; c++) {
            float F = w0;
#pragma unroll
            for (int m = 0; m < Mm; m++) {
                const int t = c + i + m;      // a-index for n = j0+c+i+m-14
                F = fmaf(wd[m * 3 + 0], a1[t], F);
                F = fmaf(wd[m * 3 + 1], a2[t], F);
                F = fmaf(wd[m * 3 + 2], a3[t], F);
            }
            const int xk = c + i + 7;         // x-index for n = j0+c+i-7
            or_[c] = fmaf(xr[xk], F, or_[c]);
            oi_[c] = fmaf(xi[xk], F, oi_[c]);
        }
    }

    float2* orow = out + (size_t)b * Tn + j0;
#pragma unroll
    for (int c = 0; c < CH; c++) orow[c] = make_float2(or_[c], oi_[c]);
}

extern "C" void kernel_launch(void* const* d_in, const int* in_sizes, int n_in,
                              void* d_out, int out_size)
{
    const float2* x = (const float2*)d_in[0];
    // d_in[1] = h_0 (unused)
    const float*  W = (const float*)d_in[2];
    float2* out = (float2*)d_out;

    const int total_threads = Bn * (Tn / CH);      // 131072
    const int grid = total_threads / TPB;          // 1024
    gmp_kernel<<<grid, TPB>>>(x, W, out);
}

// round 8
// speedup vs baseline: 1.0137x; 1.0015x over previous
#include <cuda_runtime.h>

// GMP forward:
// out[b,j] = sum_{i=0..7} xc[b, j+i-7] * F_i(j+i-7)
// F_i(n)   = W[i,0] + sum_{m=0..7} sum_{d=0..2} W[i,1+3m+d] * a(n+m-7)^(d+1)
// xc zero-extended for n<0; a(n)=|xc(n)| zero-extended.

constexpr int Bn  = 64;
constexpr int Tn  = 16384;
constexpr int Mm  = 8;
constexpr int CH  = 8;     // samples per thread
constexpr int TPB = 128;

__global__ __launch_bounds__(TPB)
void gmp_kernel(const float2* __restrict__ x,     // (B,T) complex as float2
                const float*  __restrict__ W,     // (8,25)
                float2*       __restrict__ out)   // (B,T) complex as float2
{
    __shared__ float sW[Mm * 25];
    for (int q = threadIdx.x; q < Mm * 25; q += TPB) sW[q] = W[q];
    __syncthreads();

    const int per_row = Tn / CH;                       // 2048
    const int idx = blockIdx.x * TPB + threadIdx.x;    // < B*per_row
    const int b   = idx / per_row;
    const int j0  = (idx - b * per_row) * CH;

    const float2* xrow = x + (size_t)b * Tn;

    // Load complex window: array index k corresponds to n = j0 + k - 14.
    float xr[CH + 14], xi[CH + 14];
#pragma unroll
    for (int k = 0; k < CH + 14; k++) {
        const int n = j0 + k - 14;
        float2 v;
        if (n >= 0) v = xrow[n];
        else        v = make_float2(0.f, 0.f);
        xr[k] = v.x; xi[k] = v.y;
    }

    // Envelope powers a^1, a^2, a^3 over the window.
    float a1[CH + 14], a2[CH + 14], a3[CH + 14];
#pragma unroll
    for (int k = 0; k < CH + 14; k++) {
        const float m2 = fmaf(xr[k], xr[k], xi[k] * xi[k]);
        const float a  = sqrtf(m2);
        a1[k] = a; a2[k] = m2; a3[k] = a * m2;
    }

    float or_[CH], oi_[CH];
#pragma unroll
    for (int c = 0; c < CH; c++) { or_[c] = 0.f; oi_[c] = 0.f; }

#pragma unroll
    for (int i = 0; i < Mm; i++) {
        const float w0 = sW[i * 25];
        float wd[24];
#pragma unroll
        for (int q = 0; q < 24; q++) wd[q] = sW[i * 25 + 1 + q];

#pragma unroll
        for (int c = 0; c < CH; c++) {
            float F = w0;
#pragma unroll
            for (int m = 0; m < Mm; m++) {
                const int t = c + i + m;      // a-index for n = j0+c+i+m-14
                F = fmaf(wd[m * 3 + 0], a1[t], F);
                F = fmaf(wd[m * 3 + 1], a2[t], F);
                F = fmaf(wd[m * 3 + 2], a3[t], F);
            }
            const int xk = c + i + 7;         // x-index for n = j0+c+i-7
            or_[c] = fmaf(xr[xk], F, or_[c]);
            oi_[c] = fmaf(xi[xk], F, oi_[c]);
        }
    }

    float2* orow = out + (size_t)b * Tn + j0;
#pragma unroll
    for (int c = 0; c < CH; c++) orow[c] = make_float2(or_[c], oi_[c]);
}

extern "C" void kernel_launch(void* const* d_in, const int* in_sizes, int n_in,
                              void* d_out, int out_size)
{
    const float2* x = (const float2*)d_in[0];
    // d_in[1] = h_0 (unused)
    const float*  W = (const float*)d_in[2];
    float2* out = (float2*)d_out;

    const int total_threads = Bn * (Tn / CH);      // 131072
    const int grid = total_threads / TPB;          // 1024
    gmp_kernel<<<grid, TPB>>>(x, W, out);
}

// round 9
// speedup vs baseline: 1.1104x; 1.0953x over previous
#include <cuda_runtime.h>

// GMP forward:
// out[b,j] = sum_{i=0..7} xc[b, j+i-7] * F_i(j+i-7)
// F_i(n)   = W[i,0] + sum_{m=0..7} a(n+m-7)*(w1 + a*(w2 + a*w3))   (Horner over degree)
// with (w1,w2,w3) = W[i, 1+3m+{0,1,2}]; xc,a zero-extended for n<0.

constexpr int Bn  = 64;
constexpr int Tn  = 16384;
constexpr int Mm  = 8;
constexpr int CH  = 8;     // samples per thread
constexpr int TPB = 128;
constexpr int WIN = CH + 14;   // 22
constexpr int WROW = 28;       // padded shared row (float4-friendly)

__global__ __launch_bounds__(TPB)
void gmp_kernel(const float2* __restrict__ x,     // (B,T) complex as float2
                const float*  __restrict__ W,     // (8,25)
                float2*       __restrict__ out)   // (B,T) complex as float2
{
    __shared__ float sW[Mm * WROW];
    for (int q = threadIdx.x; q < Mm * 25; q += TPB) {
        const int row = q / 25, col = q - row * 25;
        sW[row * WROW + col] = W[q];
    }
    __syncthreads();

    const int per_row = Tn / CH;                       // 2048
    const int idx = blockIdx.x * TPB + threadIdx.x;    // < B*per_row
    const int b   = idx / per_row;
    const int j0  = (idx - b * per_row) * CH;

    const float2* xrow = x + (size_t)b * Tn;

    // Vectorized complex window load: k in [0,22), n = j0 + k - 14.
    // j0 is a multiple of 8, so pair starts n = j0 + 2kp - 14 are even and
    // 16B-aligned; a pair is either fully valid (n>=0) or fully zero (n<=-2).
    float xr[WIN], xi[WIN];
#pragma unroll
    for (int kp = 0; kp < WIN / 2; kp++) {
        const int k = 2 * kp;
        const int n = j0 + k - 14;
        float4 v;
        if (n >= 0) v = *reinterpret_cast<const float4*>(xrow + n);
        else        v = make_float4(0.f, 0.f, 0.f, 0.f);
        xr[k]     = v.x; xi[k]     = v.y;
        xr[k + 1] = v.z; xi[k + 1] = v.w;
    }

    // Envelope only (Horner needs a^1 alone).
    float a[WIN];
#pragma unroll
    for (int k = 0; k < WIN; k++)
        a[k] = sqrtf(fmaf(xr[k], xr[k], xi[k] * xi[k]));

    float or_[CH], oi_[CH];
#pragma unroll
    for (int c = 0; c < CH; c++) { or_[c] = 0.f; oi_[c] = 0.f; }

#pragma unroll
    for (int i = 0; i < Mm; i++) {
        // 7x LDS.128: whole 25-float weight row for tap i.
        float wv[WROW];
#pragma unroll
        for (int q4 = 0; q4 < WROW / 4; q4++) {
            const float4 v = *reinterpret_cast<const float4*>(&sW[i * WROW + 4 * q4]);
            wv[4 * q4 + 0] = v.x; wv[4 * q4 + 1] = v.y;
            wv[4 * q4 + 2] = v.z; wv[4 * q4 + 3] = v.w;
        }
        const float w0 = wv[0];

#pragma unroll
        for (int c = 0; c < CH; c++) {
            float F = w0;
#pragma unroll
            for (int m = 0; m < Mm; m++) {
                const int   t  = c + i + m;          // a-index for n = j0+c+i+m-14
                const float av = a[t];
                const float t1 = fmaf(av, wv[3 + 3 * m], wv[2 + 3 * m]);
                const float t2 = fmaf(av, t1,            wv[1 + 3 * m]);
                F = fmaf(av, t2, F);
            }
            const int xk = c + i + 7;                // x-index for n = j0+c+i-7
            or_[c] = fmaf(xr[xk], F, or_[c]);
            oi_[c] = fmaf(xi[xk], F, oi_[c]);
        }
    }

    // Vectorized store: 4x STG.128.
    float4* orow4 = reinterpret_cast<float4*>(out + (size_t)b * Tn + j0);
#pragma unroll
    for (int c4 = 0; c4 < CH / 2; c4++)
        orow4[c4] = make_float4(or_[2 * c4], oi_[2 * c4],
                                or_[2 * c4 + 1], oi_[2 * c4 + 1]);
}

extern "C" void kernel_launch(void* const* d_in, const int* in_sizes, int n_in,
                              void* d_out, int out_size)
{
    const float2* x = (const float2*)d_in[0];
    // d_in[1] = h_0 (unused)
    const float*  W = (const float*)d_in[2];
    float2* out = (float2*)d_out;

    const int total_threads = Bn * (Tn / CH);      // 131072
    const int grid = total_threads / TPB;          // 1024
    gmp_kernel<<<grid, TPB>>>(x, W, out);
}

// round 10
// speedup vs baseline: 1.2576x; 1.1326x over previous
#include <cuda_runtime.h>
#include <cstdint>

// GMP forward:
// out[b,j] = sum_{i=0..7} xc[b, j+i-7] * F_i(j+i-7)
// F_i(n)   = W[i,0] + sum_{m=0..7} a(n+m-7)*(w1 + a*(w2 + a*w3))   (Horner over degree)
// with (w1,w2,w3) = W[i, 1+3m+{0,1,2}]; xc,a zero-extended for n<0.
// Two consecutive outputs are packed per f32x2 lane-pair (FFMA2).

constexpr int Bn  = 64;
constexpr int Tn  = 16384;
constexpr int Mm  = 8;
constexpr int CH  = 8;      // samples per thread
constexpr int TPB = 128;
constexpr int WIN = CH + 14; // 22

using u64 = unsigned long long;

__device__ __forceinline__ u64 pk2(float lo, float hi) {
    u64 r;
    unsigned lo_u = __float_as_uint(lo), hi_u = __float_as_uint(hi);
    asm("mov.b64 %0, {%1, %2};" : "=l"(r) : "r"(lo_u), "r"(hi_u));
    return r;
}
__device__ __forceinline__ void upk2(u64 v, float& lo, float& hi) {
    unsigned lo_u, hi_u;
    asm("mov.b64 {%0, %1}, %2;" : "=r"(lo_u), "=r"(hi_u) : "l"(v));
    lo = __uint_as_float(lo_u); hi = __uint_as_float(hi_u);
}
__device__ __forceinline__ u64 fma2(u64 a, u64 b, u64 c) {
    u64 r;
    asm("fma.rn.f32x2 %0, %1, %2, %3;" : "=l"(r) : "l"(a), "l"(b), "l"(c));
    return r;
}

__global__ __launch_bounds__(TPB)
void gmp_kernel(const float2* __restrict__ x,     // (B,T) complex as float2
                const float*  __restrict__ W,     // (8,25)
                float2*       __restrict__ out)   // (B,T) complex as float2
{
    // Shared weights: w0 per tap + per-(i,m) float4 triplets (w1,w2,w3,0).
    __shared__ float  sW0[Mm];
    __shared__ float4 sW4[Mm * Mm];
    for (int q = threadIdx.x; q < Mm * Mm; q += TPB) {
        const int i = q >> 3, m = q & 7;
        const float* wr = W + i * 25 + 1 + 3 * m;
        sW4[q] = make_float4(wr[0], wr[1], wr[2], 0.f);
    }
    if (threadIdx.x < Mm) sW0[threadIdx.x] = W[threadIdx.x * 25];
    __syncthreads();

    const int per_row = Tn / CH;                       // 2048
    const int idx = blockIdx.x * TPB + threadIdx.x;    // < B*per_row
    const int b   = idx / per_row;
    const int j0  = (idx - b * per_row) * CH;

    const float2* xrow = x + (size_t)b * Tn;

    // Vectorized complex window load: k in [0,22), n = j0 + k - 14.
    // j0 is a multiple of 8 -> pair starts are even & 16B-aligned; a pair is
    // fully valid (n>=0) or fully zero.
    float xr[WIN], xi[WIN];
#pragma unroll
    for (int kp = 0; kp < WIN / 2; kp++) {
        const int k = 2 * kp;
        const int n = j0 + k - 14;
        float4 v;
        if (n >= 0) v = *reinterpret_cast<const float4*>(xrow + n);
        else        v = make_float4(0.f, 0.f, 0.f, 0.f);
        xr[k]     = v.x; xi[k]     = v.y;
        xr[k + 1] = v.z; xi[k + 1] = v.w;
    }

    // Envelope a = |xc| over the window, then pack at both parities:
    //   ae[h] = (a[2h],   a[2h+1])   h = 0..10
    //   ao[h] = (a[2h+1], a[2h+2])   h = 0..9
    float a[WIN];
#pragma unroll
    for (int k = 0; k < WIN; k++)
        a[k] = sqrtf(fmaf(xr[k], xr[k], xi[k] * xi[k]));

    u64 ae[11], ao[10];
#pragma unroll
    for (int h = 0; h < 11; h++) ae[h] = pk2(a[2 * h], a[2 * h + 1]);
#pragma unroll
    for (int h = 0; h < 10; h++) ao[h] = pk2(a[2 * h + 1], a[2 * h + 2]);

    float or_[CH], oi_[CH];
#pragma unroll
    for (int c = 0; c < CH; c++) { or_[c] = 0.f; oi_[c] = 0.f; }

#pragma unroll
    for (int i = 0; i < Mm; i++) {
        const float w0 = sW0[i];
        const u64 w0p = pk2(w0, w0);
        u64 F[CH / 2];
#pragma unroll
        for (int cp = 0; cp < CH / 2; cp++) F[cp] = w0p;

#pragma unroll
        for (int m = 0; m < Mm; m++) {
            const float4 w = sW4[i * Mm + m];
            const u64 w1p = pk2(w.x, w.x);
            const u64 w2p = pk2(w.y, w.y);
            const u64 w3p = pk2(w.z, w.z);
            const int s    = i + m;        // compile-time constant
            const int base = s >> 1;
#pragma unroll
            for (int cp = 0; cp < CH / 2; cp++) {
                // pair covers t_lo = 2*cp + s, t_hi = t_lo + 1
                const u64 av = (s & 1) ? ao[base + cp] : ae[base + cp];
                u64 t1 = fma2(av, w3p, w2p);
                u64 t2 = fma2(av, t1,  w1p);
                F[cp]  = fma2(av, t2,  F[cp]);
            }
        }

        // Tail: out accumulation (scalar; xk parity varies with i).
#pragma unroll
        for (int cp = 0; cp < CH / 2; cp++) {
            float Flo, Fhi; upk2(F[cp], Flo, Fhi);
            const int c  = 2 * cp;
            const int xk = c + i + 7;      // x-index for n = j0+c+i-7
            or_[c]     = fmaf(xr[xk],     Flo, or_[c]);
            oi_[c]     = fmaf(xi[xk],     Flo, oi_[c]);
            or_[c + 1] = fmaf(xr[xk + 1], Fhi, or_[c + 1]);
            oi_[c + 1] = fmaf(xi[xk + 1], Fhi, oi_[c + 1]);
        }
    }

    // Vectorized store: 4x STG.128.
    float4* orow4 = reinterpret_cast<float4*>(out + (size_t)b * Tn + j0);
#pragma unroll
    for (int c4 = 0; c4 < CH / 2; c4++)
        orow4[c4] = make_float4(or_[2 * c4], oi_[2 * c4],
                                or_[2 * c4 + 1], oi_[2 * c4 + 1]);
}

extern "C" void kernel_launch(void* const* d_in, const int* in_sizes, int n_in,
                              void* d_out, int out_size)
{
    const float2* x = (const float2*)d_in[0];
    // d_in[1] = h_0 (unused)
    const float*  W = (const float*)d_in[2];
    float2* out = (float2*)d_out;

    const int total_threads = Bn * (Tn / CH);      // 131072
    const int grid = total_threads / TPB;          // 1024
    gmp_kernel<<<grid, TPB>>>(x, W, out);
}